// round 3
// baseline (speedup 1.0000x reference)
#include <cuda_runtime.h>
#include <cstdint>

#define NNODES 5000000
#define NGRAPHS 100000
#define NODES_PER_GRAPH 50

// L2-resident scratch (20 MB each, 80 MB total).
__device__ int   g_deg[NNODES];
__device__ float g_dis[NNODES];
__device__ float g_p[NNODES];    // xw[i] * dis[i]
__device__ float g_acc[NNODES];  // running scatter sum (init = p[i] == self-loop term)
__device__ int   g_is64;         // 1 if edge_index is int64, 0 if int32

// ---------------------------------------------------------------------------
// 0) dtype detect: int64 indices < 2^31 have all-zero high words.
__global__ void k_detect(const unsigned long long* __restrict__ e)
{
    if (threadIdx.x == 0 && blockIdx.x == 0) {
        int is64 = 1;
#pragma unroll
        for (int i = 0; i < 8; ++i)
            if ((e[i] >> 32) != 0ull) is64 = 0;
        g_is64 = is64;
    }
}

// ---------------------------------------------------------------------------
// 1) init degree to 1 (self loop)
__global__ void k_init()
{
    int i = blockIdx.x * blockDim.x + threadIdx.x;
    if (i < NNODES) g_deg[i] = 1;
}

// ---------------------------------------------------------------------------
// 2) degree count: RED.ADD to g_deg[col]. 4 edges per thread.
__global__ void k_count(const long long* __restrict__ col64,
                        const int* __restrict__ col32, long long E)
{
    long long t    = (long long)blockIdx.x * blockDim.x + threadIdx.x;
    long long base = t * 4;
    if (g_is64) {
        if (base + 3 < E) {
            ulonglong2 a = *reinterpret_cast<const ulonglong2*>(col64 + base);
            ulonglong2 b = *reinterpret_cast<const ulonglong2*>(col64 + base + 2);
            atomicAdd(&g_deg[(int)a.x], 1);
            atomicAdd(&g_deg[(int)a.y], 1);
            atomicAdd(&g_deg[(int)b.x], 1);
            atomicAdd(&g_deg[(int)b.y], 1);
        } else {
            for (long long j = base; j < E; ++j)
                atomicAdd(&g_deg[(int)col64[j]], 1);
        }
    } else {
        if (base + 3 < E) {
            int4 c = *reinterpret_cast<const int4*>(col32 + base);
            atomicAdd(&g_deg[c.x], 1);
            atomicAdd(&g_deg[c.y], 1);
            atomicAdd(&g_deg[c.z], 1);
            atomicAdd(&g_deg[c.w], 1);
        } else {
            for (long long j = base; j < E; ++j)
                atomicAdd(&g_deg[col32[j]], 1);
        }
    }
}

// ---------------------------------------------------------------------------
// 3) per-node prep: dis = rsqrt(deg); p = x*w*dis; acc starts at p (self loop)
__global__ void k_prep(const float* __restrict__ x,
                       const float* __restrict__ conv_w)
{
    int i = blockIdx.x * blockDim.x + threadIdx.x;
    if (i < NNODES) {
        float dis = rsqrtf((float)g_deg[i]);
        float p   = x[i] * conv_w[0] * dis;
        g_dis[i] = dis;
        g_p[i]   = p;
        g_acc[i] = p;
    }
}

// ---------------------------------------------------------------------------
// 4) edge scatter: acc[col] += p[row].  One 4B gather + one 4B RED per edge.
__global__ void k_edge(const long long* __restrict__ row64,
                       const long long* __restrict__ col64,
                       const int* __restrict__ row32,
                       const int* __restrict__ col32, long long E)
{
    long long t    = (long long)blockIdx.x * blockDim.x + threadIdx.x;
    long long base = t * 4;
    if (g_is64) {
        if (base + 3 < E) {
            ulonglong2 r0 = *reinterpret_cast<const ulonglong2*>(row64 + base);
            ulonglong2 r1 = *reinterpret_cast<const ulonglong2*>(row64 + base + 2);
            ulonglong2 c0 = *reinterpret_cast<const ulonglong2*>(col64 + base);
            ulonglong2 c1 = *reinterpret_cast<const ulonglong2*>(col64 + base + 2);
            float p0 = __ldg(&g_p[(int)r0.x]);
            float p1 = __ldg(&g_p[(int)r0.y]);
            float p2 = __ldg(&g_p[(int)r1.x]);
            float p3 = __ldg(&g_p[(int)r1.y]);
            atomicAdd(&g_acc[(int)c0.x], p0);
            atomicAdd(&g_acc[(int)c0.y], p1);
            atomicAdd(&g_acc[(int)c1.x], p2);
            atomicAdd(&g_acc[(int)c1.y], p3);
        } else {
            for (long long j = base; j < E; ++j)
                atomicAdd(&g_acc[(int)col64[j]], __ldg(&g_p[(int)row64[j]]));
        }
    } else {
        if (base + 3 < E) {
            int4 r = *reinterpret_cast<const int4*>(row32 + base);
            int4 c = *reinterpret_cast<const int4*>(col32 + base);
            float p0 = __ldg(&g_p[r.x]);
            float p1 = __ldg(&g_p[r.y]);
            float p2 = __ldg(&g_p[r.z]);
            float p3 = __ldg(&g_p[r.w]);
            atomicAdd(&g_acc[c.x], p0);
            atomicAdd(&g_acc[c.y], p1);
            atomicAdd(&g_acc[c.z], p2);
            atomicAdd(&g_acc[c.w], p3);
        } else {
            for (long long j = base; j < E; ++j)
                atomicAdd(&g_acc[col32[j]], __ldg(&g_p[row32[j]]));
        }
    }
}

// ---------------------------------------------------------------------------
// 5) fused h = dis*acc + conv_b  and per-graph FC (50 -> 2).
__global__ void k_fc(const float* __restrict__ conv_b,
                     const float* __restrict__ fc_w,   // [2,50] row-major
                     const float* __restrict__ fc_b,   // [2]
                     float* __restrict__ out)          // [NGRAPHS,2]
{
    int g = blockIdx.x * blockDim.x + threadIdx.x;
    if (g >= NGRAPHS) return;
    float b  = conv_b[0];
    float s0 = fc_b[0];
    float s1 = fc_b[1];
    int base = g * NODES_PER_GRAPH;
#pragma unroll
    for (int j = 0; j < NODES_PER_GRAPH; ++j) {
        float h = g_dis[base + j] * g_acc[base + j] + b;
        s0 = fmaf(h, __ldg(&fc_w[j]), s0);
        s1 = fmaf(h, __ldg(&fc_w[NODES_PER_GRAPH + j]), s1);
    }
    out[2 * g]     = s0;
    out[2 * g + 1] = s1;
}

// ---------------------------------------------------------------------------
extern "C" void kernel_launch(void* const* d_in, const int* in_sizes, int n_in,
                              void* d_out, int out_size)
{
    // Resolve inputs BY SIZE. Sizes: x=5,000,000; edge_index=160,000,000
    // (elements, dtype unknown: int32 or int64 — detected on device);
    // conv_w=1; conv_b=1 (in appearance order); fc_w=100; fc_b=2.
    const float* x      = nullptr;
    const void*  eidx   = nullptr;
    const float* conv_w = nullptr;
    const float* conv_b = nullptr;
    const float* fc_w   = nullptr;
    const float* fc_b   = nullptr;
    long long    n_edge_elems = 0;

    for (int i = 0; i < n_in; ++i) {
        long long s = in_sizes[i];
        if (s == 160000000LL)      { eidx = d_in[i]; n_edge_elems = s; }
        else if (s == 5000000LL)   { x    = (const float*)d_in[i]; }
        else if (s == 100LL)       { fc_w = (const float*)d_in[i]; }
        else if (s == 2LL)         { fc_b = (const float*)d_in[i]; }
        else if (s == 1LL) {
            if (!conv_w) conv_w = (const float*)d_in[i];
            else         conv_b = (const float*)d_in[i];
        }
    }

    float* out = (float*)d_out;
    const long long E = n_edge_elems / 2;

    const long long* row64 = (const long long*)eidx;
    const long long* col64 = row64 + E;
    const int*       row32 = (const int*)eidx;
    const int*       col32 = row32 + E;

    const int TPB = 256;
    int node_blocks = (NNODES + TPB - 1) / TPB;
    int edge_blocks = (int)((E + (long long)TPB * 4 - 1) / ((long long)TPB * 4));
    int fc_blocks   = (NGRAPHS + TPB - 1) / TPB;

    k_detect<<<1, 32>>>((const unsigned long long*)eidx);
    k_init  <<<node_blocks, TPB>>>();
    k_count <<<edge_blocks, TPB>>>(col64, col32, E);
    k_prep  <<<node_blocks, TPB>>>(x, conv_w);
    k_edge  <<<edge_blocks, TPB>>>(row64, col64, row32, col32, E);
    k_fc    <<<fc_blocks,   TPB>>>(conv_b, fc_w, fc_b, out);
}